// round 8
// baseline (speedup 1.0000x reference)
#include <cuda_runtime.h>
#include <math.h>

#define T      128
#define F      512
#define H      1024
#define RZ     1536
#define CPB    8
#define NC     128           // compute CTAs
#define NPF    20            // L2-prefetch CTAs
#define NTH    416           // 8 consumer warps + 4 producer warps + 1 poller warp
#define D      4
#define LOOKAHEAD 12
#define SLOT_BYTES (RZ * CPB * 4)     // 49152
#define SLOT_WORDS (RZ * CPB)
#define STEP_LINES (RZ * H * 4 / 128)

__device__ float    g_h[T * H];
__device__ unsigned g_cnt2[T * 8];    // per (step, 128-col group) counters, target 16

__global__ void pg_init() {
    for (int i = threadIdx.x; i < T * 8; i += blockDim.x) g_cnt2[i] = 0u;
}

__device__ __forceinline__ unsigned ld_acq(const unsigned* p) {
    unsigned v;
    asm volatile("ld.global.acquire.gpu.u32 %0, [%1];" : "=r"(v) : "l"(p) : "memory");
    return v;
}
__device__ __forceinline__ void red_rel(unsigned* p, unsigned v) {
    asm volatile("red.release.gpu.global.add.u32 [%0], %1;" :: "l"(p), "r"(v) : "memory");
}
__device__ __forceinline__ void st_rel_cta_sh(unsigned addr, unsigned v) {
    asm volatile("st.release.cta.shared.u32 [%0], %1;" :: "r"(addr), "r"(v) : "memory");
}
__device__ __forceinline__ unsigned ld_acq_cta_sh(unsigned addr) {
    unsigned v;
    asm volatile("ld.acquire.cta.shared.u32 %0, [%1];" : "=r"(v) : "r"(addr) : "memory");
    return v;
}
__device__ __forceinline__ void prefetch_l2(const void* p) {
    asm volatile("prefetch.global.L2 [%0];" :: "l"(p));
}
__device__ __forceinline__ void cp_async16(unsigned saddr, const void* gaddr) {
    asm volatile("cp.async.cg.shared.global [%0], [%1], 16;" :: "r"(saddr), "l"(gaddr));
}
__device__ __forceinline__ void cp_commit() { asm volatile("cp.async.commit_group;"); }
template<int N> __device__ __forceinline__ void cp_waitg() {
    asm volatile("cp.async.wait_group %0;" :: "n"(N));
}
__device__ __forceinline__ void bar1() {     // consumers only (256 threads)
    asm volatile("bar.sync 1, 256;" ::: "memory");
}

__global__ void __launch_bounds__(NTH, 1) pg_fused(
    const float* __restrict__ x,    // (1, T, F)
    const float* __restrict__ h0,   // (H,)
    const float* __restrict__ Ws,   // (T, RZ, H)
    const float* __restrict__ bs,   // (T, H)
    const float* __restrict__ Wo,   // (H, 2)
    const float* __restrict__ bo,   // (2,)
    float* __restrict__ out)        // [actors(2), h_final(H)]
{
    extern __shared__ char sm[];
    const int tid = threadIdx.x;

    // ================= prefetch CTAs =================
    if (blockIdx.x >= NC) {
        const int p  = blockIdx.x - NC;
        const int gt = p * NTH + tid;
        for (int t = 0; t < T; ++t) {
            if (t >= LOOKAHEAD) {
                if (tid == 0) {
                    while (ld_acq(&g_cnt2[(t - LOOKAHEAD) * 8]) != 16u) { }
                }
                __syncthreads();
            }
            const char* base = (const char*)(Ws + (size_t)t * RZ * H);
            for (int line = gt; line < STEP_LINES; line += NPF * NTH)
                prefetch_l2(base + (size_t)line * 128);
        }
        return;
    }

    // ================= compute CTAs =================
    float* s_w    = (float*)sm;                        // D x 48KB z-tiles
    float* s_red  = (float*)(sm + D * SLOT_BYTES);     // 64
    int*   s_full = (int*)(s_red + 64);                // D
    volatile int* s_consumed = (volatile int*)(s_full + D);
    unsigned* s_hflag = (unsigned*)(s_full + D + 1);   // [2][8]

    const int cg  = blockIdx.x;
    unsigned sbase  = (unsigned)__cvta_generic_to_shared(s_w);
    unsigned fbase  = (unsigned)__cvta_generic_to_shared(s_hflag);

    if (tid == 0) {
        for (int i = 0; i < D; ++i) s_full[i] = 0;
        *s_consumed = 0;
        for (int i = 0; i < 16; ++i) s_hflag[i] = 0u;
    }
    __syncthreads();

    if (tid >= 384) {
        // ---------------- poller warp: L2 counters -> smem flags ----------------
        const int g = tid - 384;                       // lane id
        if (g < 8) {
            for (int t = 1; t < T; ++t) {
                while (ld_acq(&g_cnt2[(t - 1) * 8 + g]) != 16u) { }
                st_rel_cta_sh(fbase + (unsigned)(((t & 1) * 8 + g) * 4), 1u);
            }
        }
    } else if (tid >= 256) {
        // ---------------- producers: stream full z-tiles ----------------
        const int pt = tid - 256;                      // 0..127
        const float* gcols = Ws + (size_t)cg * CPB;
        for (int t = 0; t < T; ++t) {
            while (*s_consumed < t - (D - 1)) { }
            unsigned sb = sbase + (unsigned)(t % D) * SLOT_BYTES;
            const float* gb = gcols + (size_t)t * RZ * H;
#pragma unroll
            for (int i = 0; i < 24; ++i) {
                int n   = i * 128 + pt;
                int row = n >> 1;
                int cc  = n & 1;
                unsigned soff = sb + (unsigned)(row * 32 + ((cc ^ ((row >> 2) & 1)) << 4));
                cp_async16(soff, (const void*)(gb + (size_t)row * H + cc * 4));
            }
            cp_commit();
            if (t >= 2) {
                cp_waitg<2>();
                __threadfence_block();
                atomicAdd(&s_full[(t - 2) % D], 1);
            }
        }
        cp_waitg<1>(); __threadfence_block(); atomicAdd(&s_full[(T - 2) % D], 1);
        cp_waitg<0>(); __threadfence_block(); atomicAdd(&s_full[(T - 1) % D], 1);
    } else {
        // ---------------- consumers ----------------
        const int w = tid >> 5, l = tid & 31;
        const unsigned myflag0 = fbase + (unsigned)(w * 4);        // parity 0
        const unsigned myflag1 = fbase + (unsigned)((8 + w) * 4);  // parity 1
        for (int t = 0; t < T; ++t) {
            const int slot = t % D;
            float bval = 0.f;
            if (tid < 8) bval = __ldg(&bs[t * H + cg * CPB + tid]);

            // ---- tile ready? ----
            if (tid == 0) {
                while (((volatile int*)s_full)[slot] != 128) { }
            }
            bar1();

            const float* wslot = s_w + slot * SLOT_WORDS;
            float acc[8];
#pragma unroll
            for (int j = 0; j < 8; ++j) acc[j] = 0.f;

            // ---- x-part (rows 0..511): hides the poller's L2 detect ----
#pragma unroll
            for (int i = 0; i < 2; ++i) {
                int r = w * 64 + i * 32 + l;
                float zv = __ldg(&x[t * F + r]);
                int sw = (r >> 2) & 1;
                float4 c0 = *(const float4*)(wslot + r * 8 + sw * 4);
                float4 c1 = *(const float4*)(wslot + r * 8 + (sw ^ 1) * 4);
                acc[0] = fmaf(zv, c0.x, acc[0]); acc[1] = fmaf(zv, c0.y, acc[1]);
                acc[2] = fmaf(zv, c0.z, acc[2]); acc[3] = fmaf(zv, c0.w, acc[3]);
                acc[4] = fmaf(zv, c1.x, acc[4]); acc[5] = fmaf(zv, c1.y, acc[5]);
                acc[6] = fmaf(zv, c1.z, acc[6]); acc[7] = fmaf(zv, c1.w, acc[7]);
            }

            // ---- per-warp h_{t-1} wait via smem flag (fast detect) ----
            if (t > 0) {
                const unsigned fl = (t & 1) ? myflag1 : myflag0;
                while (ld_acq_cta_sh(fl) == 0u) { }
                if (l == 0) *(volatile unsigned*)(s_hflag + (t & 1) * 8 + w) = 0u;  // reset for t+2
            }

            const float* hp = (t == 0) ? h0 : (g_h + (size_t)(t - 1) * H);
            float zv2[4];
#pragma unroll
            for (int i = 0; i < 4; ++i)
                zv2[i] = hp[w * 128 + i * 32 + l];
#pragma unroll
            for (int i = 0; i < 4; ++i) {
                int r = F + w * 128 + i * 32 + l;
                int sw = (r >> 2) & 1;
                float4 c0 = *(const float4*)(wslot + r * 8 + sw * 4);
                float4 c1 = *(const float4*)(wslot + r * 8 + (sw ^ 1) * 4);
                float zv = zv2[i];
                acc[0] = fmaf(zv, c0.x, acc[0]); acc[1] = fmaf(zv, c0.y, acc[1]);
                acc[2] = fmaf(zv, c0.z, acc[2]); acc[3] = fmaf(zv, c0.w, acc[3]);
                acc[4] = fmaf(zv, c1.x, acc[4]); acc[5] = fmaf(zv, c1.y, acc[5]);
                acc[6] = fmaf(zv, c1.z, acc[6]); acc[7] = fmaf(zv, c1.w, acc[7]);
            }

            // ---- folded warp reduce: 16 shfls instead of 40 ----
#pragma unroll
            for (int j = 0; j < 8; ++j)
                acc[j] += __shfl_xor_sync(0xffffffffu, acc[j], 16);
            float b4[4];
#pragma unroll
            for (int j = 0; j < 4; ++j) {
                b4[j] = (l & 16) ? acc[j + 4] : acc[j];
                b4[j] += __shfl_xor_sync(0xffffffffu, b4[j], 8);
            }
            float c2[2];
#pragma unroll
            for (int j = 0; j < 2; ++j) {
                c2[j] = (l & 8) ? b4[j + 2] : b4[j];
                c2[j] += __shfl_xor_sync(0xffffffffu, c2[j], 4);
            }
            float dv = (l & 4) ? c2[1] : c2[0];
            dv += __shfl_xor_sync(0xffffffffu, dv, 2);
            dv += __shfl_xor_sync(0xffffffffu, dv, 1);
            if ((l & 3) == 0) s_red[w * 8 + ((l >> 2) & 7)] = dv;
            bar1();                                   // slot fully consumed

            if (tid == 0) {                           // recycle the slot
                s_full[slot] = 0;
                __threadfence_block();
                *s_consumed = t + 1;
            }
            if (tid < 8) {
                float s = bval;
#pragma unroll
                for (int ww = 0; ww < 8; ++ww) s += s_red[ww * 8 + tid];
                float hv = tanhf(s);
                int col = cg * CPB + tid;
                g_h[(size_t)t * H + col] = hv;
                if (t == T - 1) out[2 + col] = hv;
            }
            __syncwarp(0xffffffffu);
            if (tid == 0) red_rel(&g_cnt2[t * 8 + (cg >> 4)], 1u);
        }

        // ---------------- actor head (CTA 0) ----------------
        if (cg == 0) {
            if (tid == 0) {
                for (int g = 0; g < 8; ++g)
                    while (ld_acq(&g_cnt2[(T - 1) * 8 + g]) != 16u) { }
            }
            bar1();
            const float* hf = g_h + (size_t)(T - 1) * H;
            float r0 = 0.f, r1 = 0.f;
            for (int i = tid; i < H; i += 256) {
                float hv = hf[i];
                r0 = fmaf(hv, Wo[2 * i + 0], r0);
                r1 = fmaf(hv, Wo[2 * i + 1], r1);
            }
#pragma unroll
            for (int off = 16; off >= 1; off >>= 1) {
                r0 += __shfl_xor_sync(0xffffffffu, r0, off);
                r1 += __shfl_xor_sync(0xffffffffu, r1, off);
            }
            if (l == 0) { s_red[w] = r0; s_red[8 + w] = r1; }
            bar1();
            if (tid == 0) {
                float s0 = 0.f, s1 = 0.f;
#pragma unroll
                for (int ww = 0; ww < 8; ++ww) { s0 += s_red[ww]; s1 += s_red[8 + ww]; }
                out[0] = s0 + bo[0];
                out[1] = s1 + bo[1];
            }
        }
    }
}

extern "C" void kernel_launch(void* const* d_in, const int* in_sizes, int n_in,
                              void* d_out, int out_size) {
    const float* x  = (const float*)d_in[0];
    const float* h0 = (const float*)d_in[1];
    const float* Ws = (const float*)d_in[2];
    const float* bs = (const float*)d_in[3];
    const float* Wo = (const float*)d_in[4];
    const float* bo = (const float*)d_in[5];
    float* out = (float*)d_out;

    static bool attr_set = false;
    if (!attr_set) {
        cudaFuncSetAttribute(pg_fused, cudaFuncAttributeMaxDynamicSharedMemorySize,
                             D * SLOT_BYTES + 1024);
        attr_set = true;
    }

    pg_init<<<1, 256>>>();
    pg_fused<<<NC + NPF, NTH, D * SLOT_BYTES + 1024>>>(x, h0, Ws, bs, Wo, bo, out);
}